// round 7
// baseline (speedup 1.0000x reference)
#include <cuda_runtime.h>
#include <math.h>
#include <stdint.h>

#define BB   2
#define TT   2048
#define DD   2048
#define NH   16
#define NKV  4
#define HDIM 128

// Scratch (allocation-free rule: __device__ globals)
__device__ float g_q[BB*TT*NH*HDIM];    // [B*T, 2048]
__device__ float g_k[BB*TT*NKV*HDIM];   // [B*T, 512]
__device__ float g_v[BB*TT*NKV*HDIM];   // [B*T, 512]
__device__ float g_o[BB*TT*NH*HDIM];    // [B*T, 2048] (tf32-rounded by attn)
// tf32-preconverted operands
__device__ float g_xt [BB*TT*DD];       // x as tf32 bits
__device__ float g_wqt[DD*NH*HDIM];
__device__ float g_wkt[DD*NKV*HDIM];
__device__ float g_wvt[DD*NKV*HDIM];
__device__ float g_wot[DD*DD];

__device__ __forceinline__ uint32_t f32_to_tf32(float x) {
    uint32_t r;
    asm("cvt.rna.tf32.f32 %0, %1;" : "=r"(r) : "f"(x));
    return r;
}

__device__ __forceinline__ void mma_tf32(float c[4],
                                         uint32_t a0, uint32_t a1, uint32_t a2, uint32_t a3,
                                         uint32_t b0, uint32_t b1) {
    asm volatile(
        "mma.sync.aligned.m16n8k8.row.col.f32.tf32.tf32.f32 "
        "{%0,%1,%2,%3}, {%4,%5,%6,%7}, {%8,%9}, {%0,%1,%2,%3};\n"
        : "+f"(c[0]), "+f"(c[1]), "+f"(c[2]), "+f"(c[3])
        : "r"(a0), "r"(a1), "r"(a2), "r"(a3), "r"(b0), "r"(b1));
}

__device__ __forceinline__ void cp_async16(uint32_t smem_addr, const void* gptr) {
    asm volatile("cp.async.cg.shared.global [%0], [%1], 16;\n"
                 :: "r"(smem_addr), "l"(gptr));
}
__device__ __forceinline__ void cp_commit() {
    asm volatile("cp.async.commit_group;\n" ::: "memory");
}
template <int N>
__device__ __forceinline__ void cp_wait() {
    asm volatile("cp.async.wait_group %0;\n" :: "n"(N) : "memory");
}

// ---------------------------------------------------------------------------
// tf32 pre-conversion (elementwise, float4)
// ---------------------------------------------------------------------------
__global__ __launch_bounds__(256)
void cvt_tf32_kernel(const float4* __restrict__ src, float4* __restrict__ dst, int n4) {
    int i = blockIdx.x * blockDim.x + threadIdx.x;
    if (i < n4) {
        float4 f = src[i];
        float4 o;
        o.x = __uint_as_float(f32_to_tf32(f.x));
        o.y = __uint_as_float(f32_to_tf32(f.y));
        o.z = __uint_as_float(f32_to_tf32(f.z));
        o.w = __uint_as_float(f32_to_tf32(f.w));
        dst[i] = o;
    }
}

// ---------------------------------------------------------------------------
// TF32 mma.sync GEMM, 128 threads = 4 warps, warp tile 64x64.
// BM=128, BN=128, BK=32, cp.async double-buffered, operands pre-tf32.
// Per k8-step/warp: 16 A-LDS + 16 B-LDS : 32 HMMA  (1:1)
// ---------------------------------------------------------------------------
#define APITCH 36
#define BPITCH 136
#define ASZ    (128 * APITCH)
#define BSZ    (32 * BPITCH)
#define STG    (ASZ + BSZ)
#define GEMM_SMEM_BYTES (2 * STG * 4)

__device__ __forceinline__ void gemm_body(
    const float* __restrict__ A,   // [.,K] tf32 bits, row block applied
    const float* __restrict__ B,   // [K,N] tf32 bits, col block applied
    float* __restrict__ C,
    int N, int K, uint32_t smem_base)
{
    const int tid  = threadIdx.x;
    const int wid  = tid >> 5;
    const int lane = tid & 31;
    const int g    = lane >> 2;
    const int tig  = lane & 3;

    const int warp_m = (wid & 1) * 64;   // 0 or 64
    const int warp_n = (wid >> 1) * 64;  // 0 or 64

    uint32_t* sm = (uint32_t*)__cvta_shared_to_generic(smem_base);

    const uint32_t aAddr = smem_base;
    const uint32_t bAddr = smem_base + ASZ * 4;

    float acc[4][8][4];
    #pragma unroll
    for (int i = 0; i < 4; i++)
        #pragma unroll
        for (int j = 0; j < 8; j++)
            #pragma unroll
            for (int c = 0; c < 4; c++) acc[i][j][c] = 0.0f;

    const int niter = K >> 5;

    // fill helpers: 128 threads, 8 float4 each per operand tile
    // A tile 128x32: thread t owns row t (8 float4)
    // B tile 32x128: f4 idx = v*128+tid -> row idx>>5, col4 (idx&31)*4
    {
        const float* srcA = A + (size_t)tid * K;
        uint32_t dstA = aAddr + (tid * APITCH) * 4;
        #pragma unroll
        for (int v = 0; v < 8; v++)
            cp_async16(dstA + v * 16, srcA + v * 4);
        #pragma unroll
        for (int v = 0; v < 8; v++) {
            int idx = v * 128 + tid;
            int row = idx >> 5;
            int c4  = (idx & 31) << 2;
            cp_async16(bAddr + (row * BPITCH + c4) * 4,
                       B + (size_t)row * N + c4);
        }
        cp_commit();
    }

    for (int i = 0; i < niter; i++) {
        const int cur = i & 1;
        if (i + 1 < niter) {
            const int nxt = cur ^ 1;
            const int k0 = (i + 1) << 5;
            const float* srcA = A + (size_t)tid * K + k0;
            uint32_t dstA = aAddr + (nxt * STG + tid * APITCH) * 4;
            #pragma unroll
            for (int v = 0; v < 8; v++)
                cp_async16(dstA + v * 16, srcA + v * 4);
            #pragma unroll
            for (int v = 0; v < 8; v++) {
                int idx = v * 128 + tid;
                int row = idx >> 5;
                int c4  = (idx & 31) << 2;
                cp_async16(bAddr + (nxt * STG + row * BPITCH + c4) * 4,
                           B + (size_t)(k0 + row) * N + c4);
            }
            cp_commit();
            cp_wait<1>();
        } else {
            cp_wait<0>();
        }
        __syncthreads();

        const uint32_t* As = sm + cur * STG;
        const uint32_t* Bs = As + ASZ;

        #pragma unroll
        for (int ks = 0; ks < 4; ks++) {
            const int kk = ks * 8;
            uint32_t af[4][4];
            #pragma unroll
            for (int mt = 0; mt < 4; mt++) {
                int ar = warp_m + mt * 16 + g;
                af[mt][0] = As[ar * APITCH + kk + tig];
                af[mt][1] = As[(ar + 8) * APITCH + kk + tig];
                af[mt][2] = As[ar * APITCH + kk + tig + 4];
                af[mt][3] = As[(ar + 8) * APITCH + kk + tig + 4];
            }
            uint32_t bf[8][2];
            #pragma unroll
            for (int nt = 0; nt < 8; nt++) {
                int bc = warp_n + nt * 8 + g;
                bf[nt][0] = Bs[(kk + tig) * BPITCH + bc];
                bf[nt][1] = Bs[(kk + tig + 4) * BPITCH + bc];
            }
            #pragma unroll
            for (int mt = 0; mt < 4; mt++)
                #pragma unroll
                for (int nt = 0; nt < 8; nt++)
                    mma_tf32(acc[mt][nt], af[mt][0], af[mt][1], af[mt][2], af[mt][3],
                             bf[nt][0], bf[nt][1]);
        }
        __syncthreads();
    }

    float* Cw = C + (size_t)warp_m * N + warp_n;
    #pragma unroll
    for (int mt = 0; mt < 4; mt++) {
        #pragma unroll
        for (int nt = 0; nt < 8; nt++) {
            int row = mt * 16 + g;
            int col = nt * 8 + 2 * tig;
            *(float2*)(Cw + (size_t)row * N + col) =
                make_float2(acc[mt][nt][0], acc[mt][nt][1]);
            *(float2*)(Cw + (size_t)(row + 8) * N + col) =
                make_float2(acc[mt][nt][2], acc[mt][nt][3]);
        }
    }
}

// Fused QKV projection: grid.x = 24 column tiles (16 q, 4 k, 4 v), grid.y = 32.
__global__ __launch_bounds__(128, 2)
void qkv_gemm_kernel(float* __restrict__ gq, float* __restrict__ gk,
                     float* __restrict__ gv) {
    extern __shared__ uint32_t smraw[];
    uint32_t smem_base = (uint32_t)__cvta_generic_to_shared(smraw);

    const int bx = blockIdx.x;
    const int by = blockIdx.y;

    const float* Bsel;
    float* Csel;
    int Nsel, colb;
    if (bx < 16)      { Bsel = g_wqt; Csel = gq; Nsel = 2048; colb = bx * 128; }
    else if (bx < 20) { Bsel = g_wkt; Csel = gk; Nsel = 512;  colb = (bx - 16) * 128; }
    else              { Bsel = g_wvt; Csel = gv; Nsel = 512;  colb = (bx - 20) * 128; }

    gemm_body(g_xt + (size_t)by * 128 * DD,
              Bsel + colb,
              Csel + (size_t)by * 128 * Nsel + colb,
              Nsel, DD, smem_base);
}

// Output projection: grid (N/128, M/128)
__global__ __launch_bounds__(128, 2)
void wo_gemm_kernel(float* __restrict__ C) {
    extern __shared__ uint32_t smraw[];
    uint32_t smem_base = (uint32_t)__cvta_generic_to_shared(smraw);
    const int bx = blockIdx.x;
    const int by = blockIdx.y;
    gemm_body(g_o + (size_t)by * 128 * DD,
              g_wot + bx * 128,
              C + (size_t)by * 128 * DD + bx * 128,
              DD, DD, smem_base);
}

// ---------------------------------------------------------------------------
// RoPE in-place on g_q and g_k
// ---------------------------------------------------------------------------
#define LOG2_THETA_OVER_HALF 0.20762050593046128f   // log2(10000)/64

__global__ __launch_bounds__(256)
void rope_kernel() {
    const int totq = BB * TT * NH * 64;
    const int totk = BB * TT * NKV * 64;
    int idx = blockIdx.x * blockDim.x + threadIdx.x;
    if (idx < totq) {
        int d  = idx & 63;
        int h  = (idx >> 6) % NH;
        int bt = idx / (64 * NH);
        int t  = bt & (TT - 1);
        float inv = exp2f(-(float)d * LOG2_THETA_OVER_HALF);
        float ang = (float)t * inv;
        float s, c;
        sincosf(ang, &s, &c);
        float* p = g_q + (size_t)bt * (NH * HDIM) + h * HDIM;
        float x1 = p[d], x2 = p[d + 64];
        p[d]      = x1 * c - x2 * s;
        p[d + 64] = x2 * c + x1 * s;
    } else if (idx < totq + totk) {
        int j  = idx - totq;
        int d  = j & 63;
        int h  = (j >> 6) % NKV;
        int bt = j / (64 * NKV);
        int t  = bt & (TT - 1);
        float inv = exp2f(-(float)d * LOG2_THETA_OVER_HALF);
        float ang = (float)t * inv;
        float s, c;
        sincosf(ang, &s, &c);
        float* p = g_k + (size_t)bt * (NKV * HDIM) + h * HDIM;
        float x1 = p[d], x2 = p[d + 64];
        p[d]      = x1 * c - x2 * s;
        p[d + 64] = x2 * c + x1 * s;
    }
}

// ---------------------------------------------------------------------------
// Tensor-core flash attention (tf32 mma.sync), BM=128, BN=64, HD=128.
// (round-5 version; writes g_o tf32-rounded)
// ---------------------------------------------------------------------------
#define KP 136
#define PP 72
#define ATTN_SMEM_BYTES (44096 * 4)

__global__ __launch_bounds__(256, 1)
void attn_mma_kernel(const int* __restrict__ mask, const int* __restrict__ causal_p) {
    extern __shared__ uint32_t sm[];
    uint32_t* Qs    = sm;
    uint32_t* Ks    = sm + 17408;
    uint32_t* Vs    = sm + 26112;
    uint32_t* Ps    = sm + 34816;
    int*      maskS = (int*)(sm + 44032);

    const int tid  = threadIdx.x;
    const int wid  = tid >> 5;
    const int lane = tid & 31;
    const int g    = lane >> 2;
    const int tig  = lane & 3;

    const int qb  = blockIdx.x;
    const int h   = blockIdx.y;
    const int b   = blockIdx.z;
    const int kvh = h >> 2;
    const int causal = causal_p[0];

    const float scale = 0.08838834764831845f;  // 1/sqrt(128)

    {
        const float* qbase = g_q + ((size_t)b * TT + qb * 128) * 2048 + h * HDIM;
        #pragma unroll
        for (int it = 0; it < 16; it++) {
            int task = tid + 256 * it;
            int r = task >> 5;
            int c = (task & 31) << 2;
            float4 f = *(const float4*)(qbase + (size_t)r * 2048 + c);
            uint32_t* dst = &Qs[r * KP + c];
            dst[0] = f32_to_tf32(f.x * scale);
            dst[1] = f32_to_tf32(f.y * scale);
            dst[2] = f32_to_tf32(f.z * scale);
            dst[3] = f32_to_tf32(f.w * scale);
        }
    }

    const int r0  = 16 * wid + g;
    const int r1  = r0 + 8;
    const int qg0 = qb * 128 + r0;
    const int qg1 = qb * 128 + r1;

    float accO[16][4];
    #pragma unroll
    for (int nt = 0; nt < 16; nt++)
        #pragma unroll
        for (int c = 0; c < 4; c++) accO[nt][c] = 0.0f;

    float m0 = -1e30f, m1 = -1e30f, l0 = 0.0f, l1 = 0.0f;

    const float* kbase = g_k + (size_t)b * TT * 512 + kvh * HDIM;
    const float* vbase = g_v + (size_t)b * TT * 512 + kvh * HDIM;
    const int kbmax = causal ? (2 * qb + 1) : (TT / 64 - 1);

    for (int kb = 0; kb <= kbmax; kb++) {
        const int kr0 = kb * 64;

        __syncthreads();

        #pragma unroll
        for (int it = 0; it < 8; it++) {
            int task = tid + 256 * it;
            int r = task >> 5;
            int c = (task & 31) << 2;
            float4 f = *(const float4*)(kbase + (size_t)(kr0 + r) * 512 + c);
            uint32_t* dst = &Ks[r * KP + c];
            dst[0] = f32_to_tf32(f.x);
            dst[1] = f32_to_tf32(f.y);
            dst[2] = f32_to_tf32(f.z);
            dst[3] = f32_to_tf32(f.w);
            float4 v = *(const float4*)(vbase + (size_t)(kr0 + r) * 512 + c);
            uint32_t* dvv = &Vs[r * KP + c];
            dvv[0] = f32_to_tf32(v.x);
            dvv[1] = f32_to_tf32(v.y);
            dvv[2] = f32_to_tf32(v.z);
            dvv[3] = f32_to_tf32(v.w);
        }
        if (tid < 64) maskS[tid] = mask[b * TT + kr0 + tid];
        __syncthreads();

        float sacc[8][4];
        #pragma unroll
        for (int nt = 0; nt < 8; nt++)
            #pragma unroll
            for (int c = 0; c < 4; c++) sacc[nt][c] = 0.0f;

        #pragma unroll
        for (int ks = 0; ks < 16; ks++) {
            const uint32_t* qr = &Qs[r0 * KP + ks * 8 + tig];
            uint32_t a0 = qr[0];
            uint32_t a2 = qr[4];
            uint32_t a1 = qr[8 * KP];
            uint32_t a3 = qr[8 * KP + 4];
            #pragma unroll
            for (int nt = 0; nt < 8; nt++) {
                const uint32_t* kr = &Ks[(8 * nt + g) * KP + ks * 8 + tig];
                mma_tf32(sacc[nt], a0, a1, a2, a3, kr[0], kr[4]);
            }
        }

        float lm0 = -1e30f, lm1 = -1e30f;
        #pragma unroll
        for (int nt = 0; nt < 8; nt++) {
            #pragma unroll
            for (int e = 0; e < 2; e++) {
                int c  = 8 * nt + 2 * tig + e;
                int kg = kr0 + c;
                bool mz = (maskS[c] == 0);
                if (mz || (causal && kg > qg0)) sacc[nt][e]     = -1e30f;
                if (mz || (causal && kg > qg1)) sacc[nt][e + 2] = -1e30f;
                lm0 = fmaxf(lm0, sacc[nt][e]);
                lm1 = fmaxf(lm1, sacc[nt][e + 2]);
            }
        }
        lm0 = fmaxf(lm0, __shfl_xor_sync(0xffffffffu, lm0, 1));
        lm0 = fmaxf(lm0, __shfl_xor_sync(0xffffffffu, lm0, 2));
        lm1 = fmaxf(lm1, __shfl_xor_sync(0xffffffffu, lm1, 1));
        lm1 = fmaxf(lm1, __shfl_xor_sync(0xffffffffu, lm1, 2));

        float mn0 = fmaxf(m0, lm0);
        float mn1 = fmaxf(m1, lm1);
        float esc0 = __expf(m0 - mn0);
        float esc1 = __expf(m1 - mn1);

        float ls0 = 0.0f, ls1 = 0.0f;
        #pragma unroll
        for (int nt = 0; nt < 8; nt++) {
            float p0 = __expf(sacc[nt][0] - mn0);
            float p1 = __expf(sacc[nt][1] - mn0);
            float p2 = __expf(sacc[nt][2] - mn1);
            float p3 = __expf(sacc[nt][3] - mn1);
            ls0 += p0 + p1;
            ls1 += p2 + p3;
            int c = 8 * nt + 2 * tig;
            uint32_t* d0 = &Ps[r0 * PP + c];
            uint32_t* d1 = &Ps[r1 * PP + c];
            d0[0] = f32_to_tf32(p0);
            d0[1] = f32_to_tf32(p1);
            d1[0] = f32_to_tf32(p2);
            d1[1] = f32_to_tf32(p3);
        }
        ls0 += __shfl_xor_sync(0xffffffffu, ls0, 1);
        ls0 += __shfl_xor_sync(0xffffffffu, ls0, 2);
        ls1 += __shfl_xor_sync(0xffffffffu, ls1, 1);
        ls1 += __shfl_xor_sync(0xffffffffu, ls1, 2);

        l0 = l0 * esc0 + ls0;
        l1 = l1 * esc1 + ls1;
        m0 = mn0;
        m1 = mn1;

        #pragma unroll
        for (int nt = 0; nt < 16; nt++) {
            accO[nt][0] *= esc0; accO[nt][1] *= esc0;
            accO[nt][2] *= esc1; accO[nt][3] *= esc1;
        }
        __syncwarp();

        #pragma unroll
        for (int ks = 0; ks < 8; ks++) {
            const uint32_t* pr = &Ps[r0 * PP + ks * 8 + tig];
            uint32_t a0 = pr[0];
            uint32_t a2 = pr[4];
            uint32_t a1 = pr[8 * PP];
            uint32_t a3 = pr[8 * PP + 4];
            #pragma unroll
            for (int nt = 0; nt < 16; nt++) {
                const uint32_t* vr = &Vs[(ks * 8 + tig) * KP + 8 * nt + g];
                mma_tf32(accO[nt], a0, a1, a2, a3, vr[0], vr[4 * KP]);
            }
        }
    }

    float invl0 = 1.0f / l0;
    float invl1 = 1.0f / l1;
    float* ob0 = g_o + ((size_t)b * TT + qb * 128 + r0) * 2048 + h * HDIM + 2 * tig;
    float* ob1 = g_o + ((size_t)b * TT + qb * 128 + r1) * 2048 + h * HDIM + 2 * tig;
    #pragma unroll
    for (int nt = 0; nt < 16; nt++) {
        *(float2*)(ob0 + 8 * nt) = make_float2(
            __uint_as_float(f32_to_tf32(accO[nt][0] * invl0)),
            __uint_as_float(f32_to_tf32(accO[nt][1] * invl0)));
        *(float2*)(ob1 + 8 * nt) = make_float2(
            __uint_as_float(f32_to_tf32(accO[nt][2] * invl1)),
            __uint_as_float(f32_to_tf32(accO[nt][3] * invl1)));
    }
}

// ---------------------------------------------------------------------------
extern "C" void kernel_launch(void* const* d_in, const int* in_sizes, int n_in,
                              void* d_out, int out_size) {
    const float* x      = (const float*)d_in[0];
    const int*   mask   = (const int*)d_in[1];
    const int*   causal = (const int*)d_in[2];
    const float* wq     = (const float*)d_in[3];
    const float* wk     = (const float*)d_in[4];
    const float* wv     = (const float*)d_in[5];
    const float* wo     = (const float*)d_in[6];
    float* out = (float*)d_out;

    float *gq, *gk, *gv, *xt, *wqt, *wkt, *wvt, *wot;
    cudaGetSymbolAddress((void**)&gq,  g_q);
    cudaGetSymbolAddress((void**)&gk,  g_k);
    cudaGetSymbolAddress((void**)&gv,  g_v);
    cudaGetSymbolAddress((void**)&xt,  g_xt);
    cudaGetSymbolAddress((void**)&wqt, g_wqt);
    cudaGetSymbolAddress((void**)&wkt, g_wkt);
    cudaGetSymbolAddress((void**)&wvt, g_wvt);
    cudaGetSymbolAddress((void**)&wot, g_wot);

    const int M = BB * TT;  // 4096

    cudaFuncSetAttribute(qkv_gemm_kernel, cudaFuncAttributeMaxDynamicSharedMemorySize,
                         GEMM_SMEM_BYTES);
    cudaFuncSetAttribute(wo_gemm_kernel, cudaFuncAttributeMaxDynamicSharedMemorySize,
                         GEMM_SMEM_BYTES);
    cudaFuncSetAttribute(attn_mma_kernel, cudaFuncAttributeMaxDynamicSharedMemorySize,
                         ATTN_SMEM_BYTES);

    // Pre-convert operands to tf32
    {
        int n4;
        n4 = (M * DD) / 4;
        cvt_tf32_kernel<<<(n4 + 255) / 256, 256>>>((const float4*)x,  (float4*)xt,  n4);
        n4 = (DD * NH * HDIM) / 4;
        cvt_tf32_kernel<<<(n4 + 255) / 256, 256>>>((const float4*)wq, (float4*)wqt, n4);
        n4 = (DD * NKV * HDIM) / 4;
        cvt_tf32_kernel<<<(n4 + 255) / 256, 256>>>((const float4*)wk, (float4*)wkt, n4);
        cvt_tf32_kernel<<<(n4 + 255) / 256, 256>>>((const float4*)wv, (float4*)wvt, n4);
        n4 = (DD * DD) / 4;
        cvt_tf32_kernel<<<(n4 + 255) / 256, 256>>>((const float4*)wo, (float4*)wot, n4);
    }

    // Fused QKV projection
    qkv_gemm_kernel<<<dim3(24, M / 128), 128, GEMM_SMEM_BYTES>>>(gq, gk, gv);

    // RoPE
    int rope_threads = BB * TT * (NH + NKV) * 64;
    rope_kernel<<<(rope_threads + 255) / 256, 256>>>();

    // Attention (mma.sync tensor cores), BM=128
    attn_mma_kernel<<<dim3(TT / 128, NH, BB), 256, ATTN_SMEM_BYTES>>>(mask, causal);

    // Output projection
    wo_gemm_kernel<<<dim3(DD / 128, M / 128), 128, GEMM_SMEM_BYTES>>>(out);
}

// round 8
// speedup vs baseline: 1.0495x; 1.0495x over previous
#include <cuda_runtime.h>
#include <math.h>
#include <stdint.h>

#define BB   2
#define TT   2048
#define DD   2048
#define NH   16
#define NKV  4
#define HDIM 128

// Scratch (allocation-free rule: __device__ globals)
__device__ float g_q[BB*TT*NH*HDIM];    // [B*T, 2048]
__device__ float g_k[BB*TT*NKV*HDIM];   // [B*T, 512]
__device__ float g_v[BB*TT*NKV*HDIM];   // [B*T, 512]
__device__ float g_o[BB*TT*NH*HDIM];    // [B*T, 2048] (tf32-rounded by attn)
// tf32-preconverted operands
__device__ float g_xt [BB*TT*DD];       // x as tf32 bits
__device__ float g_wqt[DD*NH*HDIM];
__device__ float g_wkt[DD*NKV*HDIM];
__device__ float g_wvt[DD*NKV*HDIM];
__device__ float g_wot[DD*DD];

__device__ __forceinline__ uint32_t f32_to_tf32(float x) {
    uint32_t r;
    asm("cvt.rna.tf32.f32 %0, %1;" : "=r"(r) : "f"(x));
    return r;
}

__device__ __forceinline__ void mma_tf32(float c[4],
                                         uint32_t a0, uint32_t a1, uint32_t a2, uint32_t a3,
                                         uint32_t b0, uint32_t b1) {
    asm volatile(
        "mma.sync.aligned.m16n8k8.row.col.f32.tf32.tf32.f32 "
        "{%0,%1,%2,%3}, {%4,%5,%6,%7}, {%8,%9}, {%0,%1,%2,%3};\n"
        : "+f"(c[0]), "+f"(c[1]), "+f"(c[2]), "+f"(c[3])
        : "r"(a0), "r"(a1), "r"(a2), "r"(a3), "r"(b0), "r"(b1));
}

__device__ __forceinline__ void cp_async16(uint32_t smem_addr, const void* gptr) {
    asm volatile("cp.async.cg.shared.global [%0], [%1], 16;\n"
                 :: "r"(smem_addr), "l"(gptr));
}
__device__ __forceinline__ void cp_commit() {
    asm volatile("cp.async.commit_group;\n" ::: "memory");
}
template <int N>
__device__ __forceinline__ void cp_wait() {
    asm volatile("cp.async.wait_group %0;\n" :: "n"(N) : "memory");
}

// ---------------------------------------------------------------------------
// tf32 pre-conversion (elementwise, float4)
// ---------------------------------------------------------------------------
__global__ __launch_bounds__(256)
void cvt_tf32_kernel(const float4* __restrict__ src, float4* __restrict__ dst, int n4) {
    int i = blockIdx.x * blockDim.x + threadIdx.x;
    if (i < n4) {
        float4 f = src[i];
        float4 o;
        o.x = __uint_as_float(f32_to_tf32(f.x));
        o.y = __uint_as_float(f32_to_tf32(f.y));
        o.z = __uint_as_float(f32_to_tf32(f.z));
        o.w = __uint_as_float(f32_to_tf32(f.w));
        dst[i] = o;
    }
}

// ---------------------------------------------------------------------------
// TF32 mma.sync GEMM: 256 threads (8 warps), warp tile 64x32.
// BM=128, BN=128, BK=32, 3-stage cp.async, ONE sync per iteration.
// ---------------------------------------------------------------------------
#define APITCH 36
#define BPITCH 136
#define ASZ    (128 * APITCH)
#define BSZ    (32 * BPITCH)
#define STG    (ASZ + BSZ)
#define NSTG   3
#define GEMM_SMEM_BYTES (NSTG * STG * 4)

__device__ __forceinline__ void gemm_fill(const float* __restrict__ A,
                                          const float* __restrict__ B,
                                          int K, int N, int k0,
                                          uint32_t aAddr, uint32_t bAddr,
                                          int a_row, int a_c4, int b_kr, int b_c4) {
    const float* srcA = A + (size_t)a_row * K + k0 + a_c4;
    uint32_t dstA = aAddr + (a_row * APITCH + a_c4) * 4;
    #pragma unroll
    for (int v = 0; v < 4; v++)
        cp_async16(dstA + v * 16, srcA + v * 4);
    #pragma unroll
    for (int v = 0; v < 4; v++) {
        int kr = b_kr + v * 8;
        cp_async16(bAddr + (kr * BPITCH + b_c4) * 4,
                   B + (size_t)(k0 + kr) * N + b_c4);
    }
}

__device__ __forceinline__ void gemm_body(
    const float* __restrict__ A,   // [.,K] tf32 bits, row block applied
    const float* __restrict__ B,   // [K,N] tf32 bits, col block applied
    float* __restrict__ C,
    int N, int K, uint32_t smem_base)
{
    const int tid  = threadIdx.x;
    const int wid  = tid >> 5;
    const int lane = tid & 31;
    const int g    = lane >> 2;
    const int tig  = lane & 3;

    const int warp_m = (wid & 1) * 64;   // 0 or 64
    const int warp_n = (wid >> 1) * 32;  // 0,32,64,96

    uint32_t* sm = (uint32_t*)__cvta_shared_to_generic(smem_base);

    const int a_row = tid >> 1;           // 0..127
    const int a_c4  = (tid & 1) << 4;     // 0 or 16
    const int b_kr  = tid >> 5;           // 0..7
    const int b_c4  = lane << 2;          // 0..124

    float acc[4][4][4];
    #pragma unroll
    for (int i = 0; i < 4; i++)
        #pragma unroll
        for (int j = 0; j < 4; j++)
            #pragma unroll
            for (int c = 0; c < 4; c++) acc[i][j][c] = 0.0f;

    const int niter = K >> 5;

    // prologue: fill tiles 0..NSTG-2
    #pragma unroll
    for (int p = 0; p < NSTG - 1; p++) {
        uint32_t ab = smem_base + (p * STG) * 4;
        gemm_fill(A, B, K, N, p << 5, ab, ab + ASZ * 4,
                  a_row, a_c4, b_kr, b_c4);
        cp_commit();
    }

    for (int i = 0; i < niter; i++) {
        cp_wait<NSTG - 2>();          // tile i resident
        __syncthreads();              // everyone done computing tile i-1

        // prefetch tile i+NSTG-1 into the stage freed at iteration i-1
        const int ft = i + NSTG - 1;
        if (ft < niter) {
            const int fs = ft % NSTG;
            uint32_t ab = smem_base + (fs * STG) * 4;
            gemm_fill(A, B, K, N, ft << 5, ab, ab + ASZ * 4,
                      a_row, a_c4, b_kr, b_c4);
        }
        cp_commit();                  // unconditional: keeps group count uniform

        const int cur = i % NSTG;
        const uint32_t* As = sm + cur * STG;
        const uint32_t* Bs = As + ASZ;

        #pragma unroll
        for (int ks = 0; ks < 4; ks++) {
            const int kk = ks * 8;
            uint32_t af[4][4];
            #pragma unroll
            for (int mt = 0; mt < 4; mt++) {
                int ar = warp_m + mt * 16 + g;
                af[mt][0] = As[ar * APITCH + kk + tig];
                af[mt][1] = As[(ar + 8) * APITCH + kk + tig];
                af[mt][2] = As[ar * APITCH + kk + tig + 4];
                af[mt][3] = As[(ar + 8) * APITCH + kk + tig + 4];
            }
            uint32_t bf[4][2];
            #pragma unroll
            for (int nt = 0; nt < 4; nt++) {
                int bc = warp_n + nt * 8 + g;
                bf[nt][0] = Bs[(kk + tig) * BPITCH + bc];
                bf[nt][1] = Bs[(kk + tig + 4) * BPITCH + bc];
            }
            #pragma unroll
            for (int mt = 0; mt < 4; mt++)
                #pragma unroll
                for (int nt = 0; nt < 4; nt++)
                    mma_tf32(acc[mt][nt], af[mt][0], af[mt][1], af[mt][2], af[mt][3],
                             bf[nt][0], bf[nt][1]);
        }
    }

    float* Cw = C + (size_t)warp_m * N + warp_n;
    #pragma unroll
    for (int mt = 0; mt < 4; mt++) {
        #pragma unroll
        for (int nt = 0; nt < 4; nt++) {
            int row = mt * 16 + g;
            int col = nt * 8 + 2 * tig;
            *(float2*)(Cw + (size_t)row * N + col) =
                make_float2(acc[mt][nt][0], acc[mt][nt][1]);
            *(float2*)(Cw + (size_t)(row + 8) * N + col) =
                make_float2(acc[mt][nt][2], acc[mt][nt][3]);
        }
    }
}

// Fused QKV projection: grid.x = 24 column tiles (16 q, 4 k, 4 v), grid.y = 32.
__global__ __launch_bounds__(256, 2)
void qkv_gemm_kernel(float* __restrict__ gq, float* __restrict__ gk,
                     float* __restrict__ gv) {
    extern __shared__ uint32_t smraw[];
    uint32_t smem_base = (uint32_t)__cvta_generic_to_shared(smraw);

    const int bx = blockIdx.x;
    const int by = blockIdx.y;

    const float* Bsel;
    float* Csel;
    int Nsel, colb;
    if (bx < 16)      { Bsel = g_wqt; Csel = gq; Nsel = 2048; colb = bx * 128; }
    else if (bx < 20) { Bsel = g_wkt; Csel = gk; Nsel = 512;  colb = (bx - 16) * 128; }
    else              { Bsel = g_wvt; Csel = gv; Nsel = 512;  colb = (bx - 20) * 128; }

    gemm_body(g_xt + (size_t)by * 128 * DD,
              Bsel + colb,
              Csel + (size_t)by * 128 * Nsel + colb,
              Nsel, DD, smem_base);
}

// Output projection: grid (N/128, M/128)
__global__ __launch_bounds__(256, 2)
void wo_gemm_kernel(float* __restrict__ C) {
    extern __shared__ uint32_t smraw[];
    uint32_t smem_base = (uint32_t)__cvta_generic_to_shared(smraw);
    const int bx = blockIdx.x;
    const int by = blockIdx.y;
    gemm_body(g_o + (size_t)by * 128 * DD,
              g_wot + bx * 128,
              C + (size_t)by * 128 * DD + bx * 128,
              DD, DD, smem_base);
}

// ---------------------------------------------------------------------------
// RoPE in-place on g_q and g_k
// ---------------------------------------------------------------------------
#define LOG2_THETA_OVER_HALF 0.20762050593046128f   // log2(10000)/64

__global__ __launch_bounds__(256)
void rope_kernel() {
    const int totq = BB * TT * NH * 64;
    const int totk = BB * TT * NKV * 64;
    int idx = blockIdx.x * blockDim.x + threadIdx.x;
    if (idx < totq) {
        int d  = idx & 63;
        int h  = (idx >> 6) % NH;
        int bt = idx / (64 * NH);
        int t  = bt & (TT - 1);
        float inv = exp2f(-(float)d * LOG2_THETA_OVER_HALF);
        float ang = (float)t * inv;
        float s, c;
        sincosf(ang, &s, &c);
        float* p = g_q + (size_t)bt * (NH * HDIM) + h * HDIM;
        float x1 = p[d], x2 = p[d + 64];
        p[d]      = x1 * c - x2 * s;
        p[d + 64] = x2 * c + x1 * s;
    } else if (idx < totq + totk) {
        int j  = idx - totq;
        int d  = j & 63;
        int h  = (j >> 6) % NKV;
        int bt = j / (64 * NKV);
        int t  = bt & (TT - 1);
        float inv = exp2f(-(float)d * LOG2_THETA_OVER_HALF);
        float ang = (float)t * inv;
        float s, c;
        sincosf(ang, &s, &c);
        float* p = g_k + (size_t)bt * (NKV * HDIM) + h * HDIM;
        float x1 = p[d], x2 = p[d + 64];
        p[d]      = x1 * c - x2 * s;
        p[d + 64] = x2 * c + x1 * s;
    }
}

// ---------------------------------------------------------------------------
// Tensor-core flash attention (tf32 mma.sync), BM=128, BN=64, HD=128.
// (round-5 version; writes g_o tf32-rounded)
// ---------------------------------------------------------------------------
#define KP 136
#define PP 72
#define ATTN_SMEM_BYTES (44096 * 4)

__global__ __launch_bounds__(256, 1)
void attn_mma_kernel(const int* __restrict__ mask, const int* __restrict__ causal_p) {
    extern __shared__ uint32_t sm[];
    uint32_t* Qs    = sm;
    uint32_t* Ks    = sm + 17408;
    uint32_t* Vs    = sm + 26112;
    uint32_t* Ps    = sm + 34816;
    int*      maskS = (int*)(sm + 44032);

    const int tid  = threadIdx.x;
    const int wid  = tid >> 5;
    const int lane = tid & 31;
    const int g    = lane >> 2;
    const int tig  = lane & 3;

    const int qb  = blockIdx.x;
    const int h   = blockIdx.y;
    const int b   = blockIdx.z;
    const int kvh = h >> 2;
    const int causal = causal_p[0];

    const float scale = 0.08838834764831845f;  // 1/sqrt(128)

    {
        const float* qbase = g_q + ((size_t)b * TT + qb * 128) * 2048 + h * HDIM;
        #pragma unroll
        for (int it = 0; it < 16; it++) {
            int task = tid + 256 * it;
            int r = task >> 5;
            int c = (task & 31) << 2;
            float4 f = *(const float4*)(qbase + (size_t)r * 2048 + c);
            uint32_t* dst = &Qs[r * KP + c];
            dst[0] = f32_to_tf32(f.x * scale);
            dst[1] = f32_to_tf32(f.y * scale);
            dst[2] = f32_to_tf32(f.z * scale);
            dst[3] = f32_to_tf32(f.w * scale);
        }
    }

    const int r0  = 16 * wid + g;
    const int r1  = r0 + 8;
    const int qg0 = qb * 128 + r0;
    const int qg1 = qb * 128 + r1;

    float accO[16][4];
    #pragma unroll
    for (int nt = 0; nt < 16; nt++)
        #pragma unroll
        for (int c = 0; c < 4; c++) accO[nt][c] = 0.0f;

    float m0 = -1e30f, m1 = -1e30f, l0 = 0.0f, l1 = 0.0f;

    const float* kbase = g_k + (size_t)b * TT * 512 + kvh * HDIM;
    const float* vbase = g_v + (size_t)b * TT * 512 + kvh * HDIM;
    const int kbmax = causal ? (2 * qb + 1) : (TT / 64 - 1);

    for (int kb = 0; kb <= kbmax; kb++) {
        const int kr0 = kb * 64;

        __syncthreads();

        #pragma unroll
        for (int it = 0; it < 8; it++) {
            int task = tid + 256 * it;
            int r = task >> 5;
            int c = (task & 31) << 2;
            float4 f = *(const float4*)(kbase + (size_t)(kr0 + r) * 512 + c);
            uint32_t* dst = &Ks[r * KP + c];
            dst[0] = f32_to_tf32(f.x);
            dst[1] = f32_to_tf32(f.y);
            dst[2] = f32_to_tf32(f.z);
            dst[3] = f32_to_tf32(f.w);
            float4 v = *(const float4*)(vbase + (size_t)(kr0 + r) * 512 + c);
            uint32_t* dvv = &Vs[r * KP + c];
            dvv[0] = f32_to_tf32(v.x);
            dvv[1] = f32_to_tf32(v.y);
            dvv[2] = f32_to_tf32(v.z);
            dvv[3] = f32_to_tf32(v.w);
        }
        if (tid < 64) maskS[tid] = mask[b * TT + kr0 + tid];
        __syncthreads();

        float sacc[8][4];
        #pragma unroll
        for (int nt = 0; nt < 8; nt++)
            #pragma unroll
            for (int c = 0; c < 4; c++) sacc[nt][c] = 0.0f;

        #pragma unroll
        for (int ks = 0; ks < 16; ks++) {
            const uint32_t* qr = &Qs[r0 * KP + ks * 8 + tig];
            uint32_t a0 = qr[0];
            uint32_t a2 = qr[4];
            uint32_t a1 = qr[8 * KP];
            uint32_t a3 = qr[8 * KP + 4];
            #pragma unroll
            for (int nt = 0; nt < 8; nt++) {
                const uint32_t* kr = &Ks[(8 * nt + g) * KP + ks * 8 + tig];
                mma_tf32(sacc[nt], a0, a1, a2, a3, kr[0], kr[4]);
            }
        }

        float lm0 = -1e30f, lm1 = -1e30f;
        #pragma unroll
        for (int nt = 0; nt < 8; nt++) {
            #pragma unroll
            for (int e = 0; e < 2; e++) {
                int c  = 8 * nt + 2 * tig + e;
                int kg = kr0 + c;
                bool mz = (maskS[c] == 0);
                if (mz || (causal && kg > qg0)) sacc[nt][e]     = -1e30f;
                if (mz || (causal && kg > qg1)) sacc[nt][e + 2] = -1e30f;
                lm0 = fmaxf(lm0, sacc[nt][e]);
                lm1 = fmaxf(lm1, sacc[nt][e + 2]);
            }
        }
        lm0 = fmaxf(lm0, __shfl_xor_sync(0xffffffffu, lm0, 1));
        lm0 = fmaxf(lm0, __shfl_xor_sync(0xffffffffu, lm0, 2));
        lm1 = fmaxf(lm1, __shfl_xor_sync(0xffffffffu, lm1, 1));
        lm1 = fmaxf(lm1, __shfl_xor_sync(0xffffffffu, lm1, 2));

        float mn0 = fmaxf(m0, lm0);
        float mn1 = fmaxf(m1, lm1);
        float esc0 = __expf(m0 - mn0);
        float esc1 = __expf(m1 - mn1);

        float ls0 = 0.0f, ls1 = 0.0f;
        #pragma unroll
        for (int nt = 0; nt < 8; nt++) {
            float p0 = __expf(sacc[nt][0] - mn0);
            float p1 = __expf(sacc[nt][1] - mn0);
            float p2 = __expf(sacc[nt][2] - mn1);
            float p3 = __expf(sacc[nt][3] - mn1);
            ls0 += p0 + p1;
            ls1 += p2 + p3;
            int c = 8 * nt + 2 * tig;
            uint32_t* d0 = &Ps[r0 * PP + c];
            uint32_t* d1 = &Ps[r1 * PP + c];
            d0[0] = f32_to_tf32(p0);
            d0[1] = f32_to_tf32(p1);
            d1[0] = f32_to_tf32(p2);
            d1[1] = f32_to_tf32(p3);
        }
        ls0 += __shfl_xor_sync(0xffffffffu, ls0, 1);
        ls0 += __shfl_xor_sync(0xffffffffu, ls0, 2);
        ls1 += __shfl_xor_sync(0xffffffffu, ls1, 1);
        ls1 += __shfl_xor_sync(0xffffffffu, ls1, 2);

        l0 = l0 * esc0 + ls0;
        l1 = l1 * esc1 + ls1;
        m0 = mn0;
        m1 = mn1;

        #pragma unroll
        for (int nt = 0; nt < 16; nt++) {
            accO[nt][0] *= esc0; accO[nt][1] *= esc0;
            accO[nt][2] *= esc1; accO[nt][3] *= esc1;
        }
        __syncwarp();

        #pragma unroll
        for (int ks = 0; ks < 8; ks++) {
            const uint32_t* pr = &Ps[r0 * PP + ks * 8 + tig];
            uint32_t a0 = pr[0];
            uint32_t a2 = pr[4];
            uint32_t a1 = pr[8 * PP];
            uint32_t a3 = pr[8 * PP + 4];
            #pragma unroll
            for (int nt = 0; nt < 16; nt++) {
                const uint32_t* vr = &Vs[(ks * 8 + tig) * KP + 8 * nt + g];
                mma_tf32(accO[nt], a0, a1, a2, a3, vr[0], vr[4 * KP]);
            }
        }
    }

    float invl0 = 1.0f / l0;
    float invl1 = 1.0f / l1;
    float* ob0 = g_o + ((size_t)b * TT + qb * 128 + r0) * 2048 + h * HDIM + 2 * tig;
    float* ob1 = g_o + ((size_t)b * TT + qb * 128 + r1) * 2048 + h * HDIM + 2 * tig;
    #pragma unroll
    for (int nt = 0; nt < 16; nt++) {
        *(float2*)(ob0 + 8 * nt) = make_float2(
            __uint_as_float(f32_to_tf32(accO[nt][0] * invl0)),
            __uint_as_float(f32_to_tf32(accO[nt][1] * invl0)));
        *(float2*)(ob1 + 8 * nt) = make_float2(
            __uint_as_float(f32_to_tf32(accO[nt][2] * invl1)),
            __uint_as_float(f32_to_tf32(accO[nt][3] * invl1)));
    }
}

// ---------------------------------------------------------------------------
extern "C" void kernel_launch(void* const* d_in, const int* in_sizes, int n_in,
                              void* d_out, int out_size) {
    const float* x      = (const float*)d_in[0];
    const int*   mask   = (const int*)d_in[1];
    const int*   causal = (const int*)d_in[2];
    const float* wq     = (const float*)d_in[3];
    const float* wk     = (const float*)d_in[4];
    const float* wv     = (const float*)d_in[5];
    const float* wo     = (const float*)d_in[6];
    float* out = (float*)d_out;

    float *gq, *gk, *gv, *xt, *wqt, *wkt, *wvt, *wot;
    cudaGetSymbolAddress((void**)&gq,  g_q);
    cudaGetSymbolAddress((void**)&gk,  g_k);
    cudaGetSymbolAddress((void**)&gv,  g_v);
    cudaGetSymbolAddress((void**)&xt,  g_xt);
    cudaGetSymbolAddress((void**)&wqt, g_wqt);
    cudaGetSymbolAddress((void**)&wkt, g_wkt);
    cudaGetSymbolAddress((void**)&wvt, g_wvt);
    cudaGetSymbolAddress((void**)&wot, g_wot);

    const int M = BB * TT;  // 4096

    cudaFuncSetAttribute(qkv_gemm_kernel, cudaFuncAttributeMaxDynamicSharedMemorySize,
                         GEMM_SMEM_BYTES);
    cudaFuncSetAttribute(wo_gemm_kernel, cudaFuncAttributeMaxDynamicSharedMemorySize,
                         GEMM_SMEM_BYTES);
    cudaFuncSetAttribute(attn_mma_kernel, cudaFuncAttributeMaxDynamicSharedMemorySize,
                         ATTN_SMEM_BYTES);

    // Pre-convert operands to tf32
    {
        int n4;
        n4 = (M * DD) / 4;
        cvt_tf32_kernel<<<(n4 + 255) / 256, 256>>>((const float4*)x,  (float4*)xt,  n4);
        n4 = (DD * NH * HDIM) / 4;
        cvt_tf32_kernel<<<(n4 + 255) / 256, 256>>>((const float4*)wq, (float4*)wqt, n4);
        n4 = (DD * NKV * HDIM) / 4;
        cvt_tf32_kernel<<<(n4 + 255) / 256, 256>>>((const float4*)wk, (float4*)wkt, n4);
        cvt_tf32_kernel<<<(n4 + 255) / 256, 256>>>((const float4*)wv, (float4*)wvt, n4);
        n4 = (DD * DD) / 4;
        cvt_tf32_kernel<<<(n4 + 255) / 256, 256>>>((const float4*)wo, (float4*)wot, n4);
    }

    // Fused QKV projection
    qkv_gemm_kernel<<<dim3(24, M / 128), 256, GEMM_SMEM_BYTES>>>(gq, gk, gv);

    // RoPE
    int rope_threads = BB * TT * (NH + NKV) * 64;
    rope_kernel<<<(rope_threads + 255) / 256, 256>>>();

    // Attention (mma.sync tensor cores), BM=128
    attn_mma_kernel<<<dim3(TT / 128, NH, BB), 256, ATTN_SMEM_BYTES>>>(mask, causal);

    // Output projection
    wo_gemm_kernel<<<dim3(DD / 128, M / 128), 256, GEMM_SMEM_BYTES>>>(out);
}

// round 9
// speedup vs baseline: 1.0813x; 1.0303x over previous
#include <cuda_runtime.h>
#include <math.h>
#include <stdint.h>

#define BB   2
#define TT   2048
#define DD   2048
#define NH   16
#define NKV  4
#define HDIM 128

// Scratch (allocation-free rule: __device__ globals)
__device__ float g_q[BB*TT*NH*HDIM];    // [B*T, 2048] (tf32+scale after rope)
__device__ float g_k[BB*TT*NKV*HDIM];   // [B*T, 512]  (tf32 after rope)
__device__ float g_v[BB*TT*NKV*HDIM];   // [B*T, 512]  (tf32 after rope pass)
__device__ float g_o[BB*TT*NH*HDIM];    // [B*T, 2048] (tf32-rounded by attn)
// tf32-preconverted operands
__device__ float g_xt [BB*TT*DD];
__device__ float g_wqt[DD*NH*HDIM];
__device__ float g_wkt[DD*NKV*HDIM];
__device__ float g_wvt[DD*NKV*HDIM];
__device__ float g_wot[DD*DD];

__device__ __forceinline__ uint32_t f32_to_tf32(float x) {
    uint32_t r;
    asm("cvt.rna.tf32.f32 %0, %1;" : "=r"(r) : "f"(x));
    return r;
}

__device__ __forceinline__ void mma_tf32(float c[4],
                                         uint32_t a0, uint32_t a1, uint32_t a2, uint32_t a3,
                                         uint32_t b0, uint32_t b1) {
    asm volatile(
        "mma.sync.aligned.m16n8k8.row.col.f32.tf32.tf32.f32 "
        "{%0,%1,%2,%3}, {%4,%5,%6,%7}, {%8,%9}, {%0,%1,%2,%3};\n"
        : "+f"(c[0]), "+f"(c[1]), "+f"(c[2]), "+f"(c[3])
        : "r"(a0), "r"(a1), "r"(a2), "r"(a3), "r"(b0), "r"(b1));
}

__device__ __forceinline__ void cp_async16(uint32_t smem_addr, const void* gptr) {
    asm volatile("cp.async.cg.shared.global [%0], [%1], 16;\n"
                 :: "r"(smem_addr), "l"(gptr));
}
__device__ __forceinline__ void cp_async4(uint32_t smem_addr, const void* gptr) {
    asm volatile("cp.async.ca.shared.global [%0], [%1], 4;\n"
                 :: "r"(smem_addr), "l"(gptr));
}
__device__ __forceinline__ void cp_commit() {
    asm volatile("cp.async.commit_group;\n" ::: "memory");
}
template <int N>
__device__ __forceinline__ void cp_wait() {
    asm volatile("cp.async.wait_group %0;\n" :: "n"(N) : "memory");
}

// ---------------------------------------------------------------------------
// Fused tf32 pre-conversion of x + all weights (single launch)
// region sizes in float4: x 2097152 | wq 1048576 | wk 262144 | wv 262144 | wo 1048576
// ---------------------------------------------------------------------------
#define CVT_N4 4718592
__global__ __launch_bounds__(256)
void cvt_all_kernel(const float4* __restrict__ x,  const float4* __restrict__ wq,
                    const float4* __restrict__ wk, const float4* __restrict__ wv,
                    const float4* __restrict__ wo,
                    float4* __restrict__ xt,  float4* __restrict__ wqt,
                    float4* __restrict__ wkt, float4* __restrict__ wvt,
                    float4* __restrict__ wot) {
    int i = blockIdx.x * blockDim.x + threadIdx.x;
    const float4* s; float4* d; int off;
    if      (i < 2097152) { s = x;  d = xt;  off = 0; }
    else if (i < 3145728) { s = wq; d = wqt; off = 2097152; }
    else if (i < 3407872) { s = wk; d = wkt; off = 3145728; }
    else if (i < 3670016) { s = wv; d = wvt; off = 3407872; }
    else if (i < CVT_N4)  { s = wo; d = wot; off = 3670016; }
    else return;
    int j = i - off;
    float4 f = s[j];
    float4 o;
    o.x = __uint_as_float(f32_to_tf32(f.x));
    o.y = __uint_as_float(f32_to_tf32(f.y));
    o.z = __uint_as_float(f32_to_tf32(f.z));
    o.w = __uint_as_float(f32_to_tf32(f.w));
    d[j] = o;
}

// ---------------------------------------------------------------------------
// TF32 mma.sync GEMM: 256 threads (8 warps), warp tile 64x32.
// BM=128, BN=128, BK=32, 3-stage cp.async, ONE sync per iteration.
// ---------------------------------------------------------------------------
#define APITCH 36
#define BPITCH 136
#define ASZ    (128 * APITCH)
#define BSZ    (32 * BPITCH)
#define STG    (ASZ + BSZ)
#define NSTG   3
#define GEMM_SMEM_BYTES (NSTG * STG * 4)

__device__ __forceinline__ void gemm_fill(const float* __restrict__ A,
                                          const float* __restrict__ B,
                                          int K, int N, int k0,
                                          uint32_t aAddr, uint32_t bAddr,
                                          int a_row, int a_c4, int b_kr, int b_c4) {
    const float* srcA = A + (size_t)a_row * K + k0 + a_c4;
    uint32_t dstA = aAddr + (a_row * APITCH + a_c4) * 4;
    #pragma unroll
    for (int v = 0; v < 4; v++)
        cp_async16(dstA + v * 16, srcA + v * 4);
    #pragma unroll
    for (int v = 0; v < 4; v++) {
        int kr = b_kr + v * 8;
        cp_async16(bAddr + (kr * BPITCH + b_c4) * 4,
                   B + (size_t)(k0 + kr) * N + b_c4);
    }
}

__device__ __forceinline__ void gemm_body(
    const float* __restrict__ A, const float* __restrict__ B,
    float* __restrict__ C, int N, int K, uint32_t smem_base)
{
    const int tid  = threadIdx.x;
    const int wid  = tid >> 5;
    const int lane = tid & 31;
    const int g    = lane >> 2;
    const int tig  = lane & 3;

    const int warp_m = (wid & 1) * 64;
    const int warp_n = (wid >> 1) * 32;

    uint32_t* sm = (uint32_t*)__cvta_shared_to_generic(smem_base);

    const int a_row = tid >> 1;
    const int a_c4  = (tid & 1) << 4;
    const int b_kr  = tid >> 5;
    const int b_c4  = lane << 2;

    float acc[4][4][4];
    #pragma unroll
    for (int i = 0; i < 4; i++)
        #pragma unroll
        for (int j = 0; j < 4; j++)
            #pragma unroll
            for (int c = 0; c < 4; c++) acc[i][j][c] = 0.0f;

    const int niter = K >> 5;

    #pragma unroll
    for (int p = 0; p < NSTG - 1; p++) {
        uint32_t ab = smem_base + (p * STG) * 4;
        gemm_fill(A, B, K, N, p << 5, ab, ab + ASZ * 4, a_row, a_c4, b_kr, b_c4);
        cp_commit();
    }

    for (int i = 0; i < niter; i++) {
        cp_wait<NSTG - 2>();
        __syncthreads();

        const int ft = i + NSTG - 1;
        if (ft < niter) {
            const int fs = ft % NSTG;
            uint32_t ab = smem_base + (fs * STG) * 4;
            gemm_fill(A, B, K, N, ft << 5, ab, ab + ASZ * 4, a_row, a_c4, b_kr, b_c4);
        }
        cp_commit();

        const int cur = i % NSTG;
        const uint32_t* As = sm + cur * STG;
        const uint32_t* Bs = As + ASZ;

        #pragma unroll
        for (int ks = 0; ks < 4; ks++) {
            const int kk = ks * 8;
            uint32_t af[4][4];
            #pragma unroll
            for (int mt = 0; mt < 4; mt++) {
                int ar = warp_m + mt * 16 + g;
                af[mt][0] = As[ar * APITCH + kk + tig];
                af[mt][1] = As[(ar + 8) * APITCH + kk + tig];
                af[mt][2] = As[ar * APITCH + kk + tig + 4];
                af[mt][3] = As[(ar + 8) * APITCH + kk + tig + 4];
            }
            uint32_t bf[4][2];
            #pragma unroll
            for (int nt = 0; nt < 4; nt++) {
                int bc = warp_n + nt * 8 + g;
                bf[nt][0] = Bs[(kk + tig) * BPITCH + bc];
                bf[nt][1] = Bs[(kk + tig + 4) * BPITCH + bc];
            }
            #pragma unroll
            for (int mt = 0; mt < 4; mt++)
                #pragma unroll
                for (int nt = 0; nt < 4; nt++)
                    mma_tf32(acc[mt][nt], af[mt][0], af[mt][1], af[mt][2], af[mt][3],
                             bf[nt][0], bf[nt][1]);
        }
    }

    float* Cw = C + (size_t)warp_m * N + warp_n;
    #pragma unroll
    for (int mt = 0; mt < 4; mt++) {
        #pragma unroll
        for (int nt = 0; nt < 4; nt++) {
            int row = mt * 16 + g;
            int col = nt * 8 + 2 * tig;
            *(float2*)(Cw + (size_t)row * N + col) =
                make_float2(acc[mt][nt][0], acc[mt][nt][1]);
            *(float2*)(Cw + (size_t)(row + 8) * N + col) =
                make_float2(acc[mt][nt][2], acc[mt][nt][3]);
        }
    }
}

__global__ __launch_bounds__(256, 2)
void qkv_gemm_kernel(float* __restrict__ gq, float* __restrict__ gk,
                     float* __restrict__ gv) {
    extern __shared__ uint32_t smraw[];
    uint32_t smem_base = (uint32_t)__cvta_generic_to_shared(smraw);

    const int bx = blockIdx.x;
    const int by = blockIdx.y;

    const float* Bsel;
    float* Csel;
    int Nsel, colb;
    if (bx < 16)      { Bsel = g_wqt; Csel = gq; Nsel = 2048; colb = bx * 128; }
    else if (bx < 20) { Bsel = g_wkt; Csel = gk; Nsel = 512;  colb = (bx - 16) * 128; }
    else              { Bsel = g_wvt; Csel = gv; Nsel = 512;  colb = (bx - 20) * 128; }

    gemm_body(g_xt + (size_t)by * 128 * DD, Bsel + colb,
              Csel + (size_t)by * 128 * Nsel + colb, Nsel, DD, smem_base);
}

__global__ __launch_bounds__(256, 2)
void wo_gemm_kernel(float* __restrict__ C) {
    extern __shared__ uint32_t smraw[];
    uint32_t smem_base = (uint32_t)__cvta_generic_to_shared(smraw);
    gemm_body(g_o + (size_t)blockIdx.y * 128 * DD,
              g_wot + blockIdx.x * 128,
              C + (size_t)blockIdx.y * 128 * DD + blockIdx.x * 128,
              DD, DD, smem_base);
}

// ---------------------------------------------------------------------------
// RoPE in-place on g_q (scale+tf32 folded), g_k (tf32 folded), g_v (tf32 pass)
// ---------------------------------------------------------------------------
#define LOG2_THETA_OVER_HALF 0.20762050593046128f   // log2(10000)/64
#define ROPE_TOTQ (BB*TT*NH*64)
#define ROPE_TOTK (BB*TT*NKV*64)
#define ROPE_TOTV (BB*TT*NKV*HDIM)
#define ROPE_TOT  (ROPE_TOTQ + ROPE_TOTK + ROPE_TOTV)

__global__ __launch_bounds__(256)
void rope_kernel() {
    const float scale = 0.08838834764831845f;  // 1/sqrt(128)
    int idx = blockIdx.x * blockDim.x + threadIdx.x;
    if (idx < ROPE_TOTQ) {
        int d  = idx & 63;
        int h  = (idx >> 6) % NH;
        int bt = idx / (64 * NH);
        int t  = bt & (TT - 1);
        float inv = exp2f(-(float)d * LOG2_THETA_OVER_HALF);
        float ang = (float)t * inv;
        float s, c;
        sincosf(ang, &s, &c);
        float* p = g_q + (size_t)bt * (NH * HDIM) + h * HDIM;
        float x1 = p[d], x2 = p[d + 64];
        p[d]      = __uint_as_float(f32_to_tf32((x1 * c - x2 * s) * scale));
        p[d + 64] = __uint_as_float(f32_to_tf32((x2 * c + x1 * s) * scale));
    } else if (idx < ROPE_TOTQ + ROPE_TOTK) {
        int j  = idx - ROPE_TOTQ;
        int d  = j & 63;
        int h  = (j >> 6) % NKV;
        int bt = j / (64 * NKV);
        int t  = bt & (TT - 1);
        float inv = exp2f(-(float)d * LOG2_THETA_OVER_HALF);
        float ang = (float)t * inv;
        float s, c;
        sincosf(ang, &s, &c);
        float* p = g_k + (size_t)bt * (NKV * HDIM) + h * HDIM;
        float x1 = p[d], x2 = p[d + 64];
        p[d]      = __uint_as_float(f32_to_tf32(x1 * c - x2 * s));
        p[d + 64] = __uint_as_float(f32_to_tf32(x2 * c + x1 * s));
    } else if (idx < ROPE_TOT) {
        int j = idx - ROPE_TOTQ - ROPE_TOTK;
        g_v[j] = __uint_as_float(f32_to_tf32(g_v[j]));
    }
}

// ---------------------------------------------------------------------------
// Tensor-core flash attention (tf32 mma.sync), BM=128, BN=64, HD=128.
// Inputs pre-rounded to tf32 (q pre-scaled). All smem fills via cp.async:
//  - Qs once; Ks single-buffered, prefetched after S-MMA (overlaps softmax+PV)
//  - Vs double-buffered (prefetch overlaps S+softmax); mask double-buffered.
// smem words: Qs[128][136]=17408 | Ks[64][136]=8704 | Vs[2][64][136]=17408 |
//             Ps[128][72]=9216 | mask[2][64]=128  -> 52864 words = 211456 B
// ---------------------------------------------------------------------------
#define KP 136
#define PP 72
#define QS_OFF   0
#define KS_OFF   17408
#define VS_OFF   26112
#define PS_OFF   43520
#define MASK_OFF 52736
#define ATTN_SMEM_BYTES ((52736 + 128) * 4)

__global__ __launch_bounds__(256, 1)
void attn_mma_kernel(const int* __restrict__ mask, const int* __restrict__ causal_p) {
    extern __shared__ uint32_t sm[];
    const uint32_t smem_base = (uint32_t)__cvta_generic_to_shared(sm);
    uint32_t* Qs    = sm + QS_OFF;
    uint32_t* Ks    = sm + KS_OFF;
    uint32_t* Ps    = sm + PS_OFF;
    int*      maskS = (int*)(sm + MASK_OFF);

    const int tid  = threadIdx.x;
    const int wid  = tid >> 5;
    const int lane = tid & 31;
    const int g    = lane >> 2;
    const int tig  = lane & 3;

    const int qb  = (gridDim.x - 1) - blockIdx.x;   // LPT: long CTAs first
    const int h   = blockIdx.y;
    const int b   = blockIdx.z;
    const int kvh = h >> 2;
    const int causal = causal_p[0];

    const float* qbase = g_q + ((size_t)b * TT + qb * 128) * 2048 + h * HDIM;
    const float* kbase = g_k + (size_t)b * TT * 512 + kvh * HDIM;
    const float* vbase = g_v + (size_t)b * TT * 512 + kvh * HDIM;
    const int*   mbase = mask + b * TT;

    // ---- prologue: async fill Q (whole), K0, V0 into buf0, mask0 ----
    #pragma unroll
    for (int it = 0; it < 16; it++) {
        int task = tid + 256 * it;
        int r = task >> 5;
        int c = (task & 31) << 2;
        cp_async16(smem_base + (QS_OFF + r * KP + c) * 4,
                   qbase + (size_t)r * 2048 + c);
    }
    #pragma unroll
    for (int it = 0; it < 8; it++) {
        int task = tid + 256 * it;
        int r = task >> 5;
        int c = (task & 31) << 2;
        cp_async16(smem_base + (KS_OFF + r * KP + c) * 4,
                   kbase + (size_t)r * 512 + c);
        cp_async16(smem_base + (VS_OFF + r * KP + c) * 4,
                   vbase + (size_t)r * 512 + c);
    }
    if (tid < 64)
        cp_async4(smem_base + (MASK_OFF + tid) * 4, mbase + tid);
    cp_commit();

    const int r0  = 16 * wid + g;
    const int r1  = r0 + 8;
    const int qg0 = qb * 128 + r0;
    const int qg1 = qb * 128 + r1;

    float accO[16][4];
    #pragma unroll
    for (int nt = 0; nt < 16; nt++)
        #pragma unroll
        for (int c = 0; c < 4; c++) accO[nt][c] = 0.0f;

    float m0 = -1e30f, m1 = -1e30f, l0 = 0.0f, l1 = 0.0f;

    const int kbmax = causal ? (2 * qb + 1) : (TT / 64 - 1);

    for (int kb = 0; kb <= kbmax; kb++) {
        const int kr0 = kb * 64;
        const int cbuf = kb & 1;

        cp_wait<0>();          // K[kb], V[kb], mask[kb] (and Q on kb=0) arrived
        __syncthreads();       // visible to all threads; prior PV done

        // ---- S = Q @ K^T : warp computes 16 x 64 ----
        float sacc[8][4];
        #pragma unroll
        for (int nt = 0; nt < 8; nt++)
            #pragma unroll
            for (int c = 0; c < 4; c++) sacc[nt][c] = 0.0f;

        #pragma unroll
        for (int ks = 0; ks < 16; ks++) {
            const uint32_t* qr = &Qs[r0 * KP + ks * 8 + tig];
            uint32_t a0 = qr[0];
            uint32_t a2 = qr[4];
            uint32_t a1 = qr[8 * KP];
            uint32_t a3 = qr[8 * KP + 4];
            #pragma unroll
            for (int nt = 0; nt < 8; nt++) {
                const uint32_t* kr = &Ks[(8 * nt + g) * KP + ks * 8 + tig];
                mma_tf32(sacc[nt], a0, a1, a2, a3, kr[0], kr[4]);
            }
        }
        __syncthreads();       // all warps done reading Ks

        // ---- prefetch K[kb+1], V[kb+1] (alt buf), mask[kb+1] ----
        if (kb < kbmax) {
            const int nr0 = kr0 + 64;
            const int nbuf = (kb + 1) & 1;
            #pragma unroll
            for (int it = 0; it < 8; it++) {
                int task = tid + 256 * it;
                int r = task >> 5;
                int c = (task & 31) << 2;
                cp_async16(smem_base + (KS_OFF + r * KP + c) * 4,
                           kbase + (size_t)(nr0 + r) * 512 + c);
                cp_async16(smem_base + (VS_OFF + nbuf * 8704 + r * KP + c) * 4,
                           vbase + (size_t)(nr0 + r) * 512 + c);
            }
            if (tid < 64)
                cp_async4(smem_base + (MASK_OFF + nbuf * 64 + tid) * 4,
                          mbase + nr0 + tid);
        }
        cp_commit();

        // ---- mask + warp-local row max ----
        const int* mcur = maskS + cbuf * 64;
        float lm0 = -1e30f, lm1 = -1e30f;
        #pragma unroll
        for (int nt = 0; nt < 8; nt++) {
            #pragma unroll
            for (int e = 0; e < 2; e++) {
                int c  = 8 * nt + 2 * tig + e;
                int kg = kr0 + c;
                bool mz = (mcur[c] == 0);
                if (mz || (causal && kg > qg0)) sacc[nt][e]     = -1e30f;
                if (mz || (causal && kg > qg1)) sacc[nt][e + 2] = -1e30f;
                lm0 = fmaxf(lm0, sacc[nt][e]);
                lm1 = fmaxf(lm1, sacc[nt][e + 2]);
            }
        }
        lm0 = fmaxf(lm0, __shfl_xor_sync(0xffffffffu, lm0, 1));
        lm0 = fmaxf(lm0, __shfl_xor_sync(0xffffffffu, lm0, 2));
        lm1 = fmaxf(lm1, __shfl_xor_sync(0xffffffffu, lm1, 1));
        lm1 = fmaxf(lm1, __shfl_xor_sync(0xffffffffu, lm1, 2));

        float mn0 = fmaxf(m0, lm0);
        float mn1 = fmaxf(m1, lm1);
        float esc0 = __expf(m0 - mn0);
        float esc1 = __expf(m1 - mn1);

        float ls0 = 0.0f, ls1 = 0.0f;
        #pragma unroll
        for (int nt = 0; nt < 8; nt++) {
            float p0 = __expf(sacc[nt][0] - mn0);
            float p1 = __expf(sacc[nt][1] - mn0);
            float p2 = __expf(sacc[nt][2] - mn1);
            float p3 = __expf(sacc[nt][3] - mn1);
            ls0 += p0 + p1;
            ls1 += p2 + p3;
            int c = 8 * nt + 2 * tig;
            uint32_t* d0 = &Ps[r0 * PP + c];
            uint32_t* d1 = &Ps[r1 * PP + c];
            d0[0] = f32_to_tf32(p0);
            d0[1] = f32_to_tf32(p1);
            d1[0] = f32_to_tf32(p2);
            d1[1] = f32_to_tf32(p3);
        }
        ls0 += __shfl_xor_sync(0xffffffffu, ls0, 1);
        ls0 += __shfl_xor_sync(0xffffffffu, ls0, 2);
        ls1 += __shfl_xor_sync(0xffffffffu, ls1, 1);
        ls1 += __shfl_xor_sync(0xffffffffu, ls1, 2);

        l0 = l0 * esc0 + ls0;
        l1 = l1 * esc1 + ls1;
        m0 = mn0;
        m1 = mn1;

        #pragma unroll
        for (int nt = 0; nt < 16; nt++) {
            accO[nt][0] *= esc0; accO[nt][1] *= esc0;
            accO[nt][2] *= esc1; accO[nt][3] *= esc1;
        }
        __syncwarp();   // P visible to own warp

        // ---- O += P @ V (current buffer) ----
        const uint32_t* Vc = sm + VS_OFF + cbuf * 8704;
        #pragma unroll
        for (int ks = 0; ks < 8; ks++) {
            const uint32_t* pr = &Ps[r0 * PP + ks * 8 + tig];
            uint32_t a0 = pr[0];
            uint32_t a2 = pr[4];
            uint32_t a1 = pr[8 * PP];
            uint32_t a3 = pr[8 * PP + 4];
            #pragma unroll
            for (int nt = 0; nt < 16; nt++) {
                const uint32_t* vr = &Vc[(ks * 8 + tig) * KP + 8 * nt + g];
                mma_tf32(accO[nt], a0, a1, a2, a3, vr[0], vr[4 * KP]);
            }
        }
    }

    float invl0 = 1.0f / l0;
    float invl1 = 1.0f / l1;
    float* ob0 = g_o + ((size_t)b * TT + qb * 128 + r0) * 2048 + h * HDIM + 2 * tig;
    float* ob1 = g_o + ((size_t)b * TT + qb * 128 + r1) * 2048 + h * HDIM + 2 * tig;
    #pragma unroll
    for (int nt = 0; nt < 16; nt++) {
        *(float2*)(ob0 + 8 * nt) = make_float2(
            __uint_as_float(f32_to_tf32(accO[nt][0] * invl0)),
            __uint_as_float(f32_to_tf32(accO[nt][1] * invl0)));
        *(float2*)(ob1 + 8 * nt) = make_float2(
            __uint_as_float(f32_to_tf32(accO[nt][2] * invl1)),
            __uint_as_float(f32_to_tf32(accO[nt][3] * invl1)));
    }
}

// ---------------------------------------------------------------------------
extern "C" void kernel_launch(void* const* d_in, const int* in_sizes, int n_in,
                              void* d_out, int out_size) {
    const float* x      = (const float*)d_in[0];
    const int*   mask   = (const int*)d_in[1];
    const int*   causal = (const int*)d_in[2];
    const float* wq     = (const float*)d_in[3];
    const float* wk     = (const float*)d_in[4];
    const float* wv     = (const float*)d_in[5];
    const float* wo     = (const float*)d_in[6];
    float* out = (float*)d_out;

    float *gq, *gk, *gv, *xt, *wqt, *wkt, *wvt, *wot;
    cudaGetSymbolAddress((void**)&gq,  g_q);
    cudaGetSymbolAddress((void**)&gk,  g_k);
    cudaGetSymbolAddress((void**)&gv,  g_v);
    cudaGetSymbolAddress((void**)&xt,  g_xt);
    cudaGetSymbolAddress((void**)&wqt, g_wqt);
    cudaGetSymbolAddress((void**)&wkt, g_wkt);
    cudaGetSymbolAddress((void**)&wvt, g_wvt);
    cudaGetSymbolAddress((void**)&wot, g_wot);

    const int M = BB * TT;  // 4096

    cudaFuncSetAttribute(qkv_gemm_kernel, cudaFuncAttributeMaxDynamicSharedMemorySize,
                         GEMM_SMEM_BYTES);
    cudaFuncSetAttribute(wo_gemm_kernel, cudaFuncAttributeMaxDynamicSharedMemorySize,
                         GEMM_SMEM_BYTES);
    cudaFuncSetAttribute(attn_mma_kernel, cudaFuncAttributeMaxDynamicSharedMemorySize,
                         ATTN_SMEM_BYTES);

    // Pre-convert operands to tf32 (single fused launch)
    cvt_all_kernel<<<(CVT_N4 + 255) / 256, 256>>>(
        (const float4*)x,  (const float4*)wq, (const float4*)wk,
        (const float4*)wv, (const float4*)wo,
        (float4*)xt, (float4*)wqt, (float4*)wkt, (float4*)wvt, (float4*)wot);

    // Fused QKV projection
    qkv_gemm_kernel<<<dim3(24, M / 128), 256, GEMM_SMEM_BYTES>>>(gq, gk, gv);

    // RoPE (+ tf32 rounding of q (scaled), k, v)
    rope_kernel<<<(ROPE_TOT + 255) / 256, 256>>>();

    // Attention (mma.sync tensor cores), BM=128, async pipelined
    attn_mma_kernel<<<dim3(TT / 128, NH, BB), 256, ATTN_SMEM_BYTES>>>(mask, causal);

    // Output projection
    wo_gemm_kernel<<<dim3(DD / 128, M / 128), 256, GEMM_SMEM_BYTES>>>(out);
}